// round 15
// baseline (speedup 1.0000x reference)
#include <cuda_runtime.h>
#include <cuda_fp16.h>
#include <cstdint>

// ---------------------------------------------------------------------------
// AttentionRAR: x -> qkv GEMM -> causal flash attention -> proj GEMM (+bias)
// B=4, N=2048, C=1024, H=16, D=64
// All matmuls pure-fp16 mma.sync with fp32 accumulate.
// Weights consumed K-major via ldmatrix.trans (no transpose kernels).
// R15: fixes R14's causal-mask condition (mask vs first row, not last).
// ---------------------------------------------------------------------------

#define BATCH 4
#define SEQ   2048
#define CH    1024
#define HEADS 16
#define HDIM  64
#define ROWS  (BATCH * SEQ)       // 8192
#define QKV_C (3 * CH)            // 3072

// Scratch
__device__ __align__(1024) __half g_qh [(size_t)ROWS * QKV_C];  // qkv (fp16)
__device__ __align__(1024) __half g_xh [(size_t)ROWS * CH];     // x (fp16)
__device__ __align__(1024) __half g_ah [(size_t)ROWS * CH];     // attn out (fp16)
__device__ __align__(1024) __half g_wq16[(size_t)CH * QKV_C];   // Wqkv fp16 [k][n]
__device__ __align__(1024) __half g_wp16[(size_t)CH * CH];      // Wproj fp16 [k][n]

// ======================= helpers ===========================================
__device__ __forceinline__ uint32_t smem_u32(const void* p) {
    uint32_t a;
    asm("{ .reg .u64 t; cvta.to.shared.u64 t, %1; cvt.u32.u64 %0, t; }"
        : "=r"(a) : "l"(p));
    return a;
}

#define CP_ASYNC16(sm, gp) \
    asm volatile("cp.async.cg.shared.global [%0], [%1], 16;" :: "r"(sm), "l"(gp))
#define CP_COMMIT() asm volatile("cp.async.commit_group;" ::: "memory")
#define CP_WAIT1()  asm volatile("cp.async.wait_group 1;" ::: "memory")

__device__ __forceinline__ void ldsm_x4(uint32_t& r0, uint32_t& r1,
                                        uint32_t& r2, uint32_t& r3, uint32_t a) {
    asm volatile("ldmatrix.sync.aligned.m8n8.x4.shared.b16 {%0,%1,%2,%3}, [%4];"
                 : "=r"(r0), "=r"(r1), "=r"(r2), "=r"(r3) : "r"(a));
}
__device__ __forceinline__ void ldsm_x4t(uint32_t& r0, uint32_t& r1,
                                         uint32_t& r2, uint32_t& r3, uint32_t a) {
    asm volatile("ldmatrix.sync.aligned.m8n8.x4.trans.shared.b16 {%0,%1,%2,%3}, [%4];"
                 : "=r"(r0), "=r"(r1), "=r"(r2), "=r"(r3) : "r"(a));
}
__device__ __forceinline__ void mma16816(float* c, const uint32_t* a,
                                         const uint32_t* b) {
    asm volatile("mma.sync.aligned.m16n8k16.row.col.f32.f16.f16.f32 "
                 "{%0,%1,%2,%3}, {%4,%5,%6,%7}, {%8,%9}, {%0,%1,%2,%3};"
                 : "+f"(c[0]), "+f"(c[1]), "+f"(c[2]), "+f"(c[3])
                 : "r"(a[0]), "r"(a[1]), "r"(a[2]), "r"(a[3]),
                   "r"(b[0]), "r"(b[1]));
}
__device__ __forceinline__ uint32_t pack_h2(float a, float b) {
    __half2 h = __floats2half2_rn(a, b);
    return *(uint32_t*)&h;
}

// ---------------------------------------------------------------------------
// Conversions: flat fp32 -> fp16 rounding (layout preserved)
// ---------------------------------------------------------------------------
__global__ void round_flat(const float* __restrict__ in, __half* __restrict__ out,
                           int n4)
{
    int i = blockIdx.x * blockDim.x + threadIdx.x;
    if (i < n4) {
        float4 v = ((const float4*)in)[i];
        uint32_t lo = pack_h2(v.x, v.y);
        uint32_t hi = pack_h2(v.z, v.w);
        ((uint2*)out)[i] = make_uint2(lo, hi);
    }
}

// ---------------------------------------------------------------------------
// mma.sync fp16 GEMM, fp32 acc: C[M,N] = A[M,K] * B[K,N] (+bias)
// A row-major (ldmatrix), B K-major (ldmatrix.trans — like attention's V path).
// 128x128 CTA tile, BK=32, 8 warps (2x4), warp tile 64x32, 3-stage ring.
// MODE 0: fp32 out + bias. MODE 1: fp16 out.
// ---------------------------------------------------------------------------
#define BK    32
#define LDA_S 40       // A smem row stride (halves)
#define LDB_S 136      // B smem row stride (halves)
#define ASTG_A (128 * LDA_S * 2)    // 10240
#define ASTG_B (BK * LDB_S * 2)     // 8704
#define NSTG 3
#define GSM_BYTES (NSTG * (ASTG_A + ASTG_B))   // 56832

template<int MODE>
__global__ __launch_bounds__(256)
void gemm_mma(const __half* __restrict__ A, int lda,
              const __half* __restrict__ B,
              const float* __restrict__ bias, float* __restrict__ C,
              __half* __restrict__ Ch, int N, int nchunk)
{
    extern __shared__ __align__(128) char gsm[];
    const uint32_t sb = smem_u32(gsm);

    const int tid  = threadIdx.x;
    const int lane = tid & 31;
    const int warp = tid >> 5;
    const int wm   = warp >> 2;      // 0..1
    const int wn   = warp & 3;       // 0..3
    const int m0   = blockIdx.y * 128;
    const int n0   = blockIdx.x * 128;

    const int ar = tid >> 1;               // A row
    const int aj = (tid & 1) * 16;         // A col base (halves)
    const int bkr = tid >> 4;              // B k-row (0..15), +16 via i
    const int bnc = (tid & 15) * 8;        // B n offset (halves)

    auto load = [&](int kc, int buf) {
        const uint32_t sA = sb + buf * ASTG_A;
        const uint32_t sB = sb + NSTG * ASTG_A + buf * ASTG_B;
        const __half* Ag = A + (size_t)(m0 + ar) * lda + kc * BK + aj;
        CP_ASYNC16(sA + (uint32_t)(ar * LDA_S + aj) * 2, Ag);
        CP_ASYNC16(sA + (uint32_t)(ar * LDA_S + aj + 8) * 2, Ag + 8);
        #pragma unroll
        for (int i = 0; i < 2; i++) {
            int kr = bkr + i * 16;
            CP_ASYNC16(sB + (uint32_t)(kr * LDB_S + bnc) * 2,
                       B + (size_t)(kc * BK + kr) * N + n0 + bnc);
        }
    };

    const int lmat = lane >> 3;
    const int lrow = lane & 7;
    const int a_row_base = wm * 64 + ((lmat & 1) << 3) + lrow;
    const int a_k_off    = (lmat >> 1) << 3;
    const int bt_r = ((lmat & 1) << 3) + lrow;   // B: k offset (trans path)
    const int bt_c = (lmat >> 1) << 3;           // B: n offset

    float acc[4][4][4];
    #pragma unroll
    for (int i = 0; i < 4; i++)
        #pragma unroll
        for (int j = 0; j < 4; j++)
            #pragma unroll
            for (int q = 0; q < 4; q++) acc[i][j][q] = 0.0f;

    load(0, 0); CP_COMMIT();
    load(1, 1); CP_COMMIT();

    for (int t = 0; t < nchunk; t++) {
        const int buf = t % NSTG;
        CP_WAIT1();
        __syncthreads();
        if (t + 2 < nchunk) load(t + 2, (t + 2) % NSTG);
        CP_COMMIT();

        const uint32_t sA = sb + buf * ASTG_A;
        const uint32_t sB = sb + NSTG * ASTG_A + buf * ASTG_B;
        #pragma unroll
        for (int ks = 0; ks < 2; ks++) {
            uint32_t a[4][4];
            #pragma unroll
            for (int mt = 0; mt < 4; mt++)
                ldsm_x4(a[mt][0], a[mt][1], a[mt][2], a[mt][3],
                        sA + (uint32_t)((a_row_base + mt * 16) * LDA_S
                                        + ks * 16 + a_k_off) * 2);
            uint32_t bb[2][4];
            #pragma unroll
            for (int nt = 0; nt < 2; nt++)
                ldsm_x4t(bb[nt][0], bb[nt][1], bb[nt][2], bb[nt][3],
                         sB + (uint32_t)((ks * 16 + bt_r) * LDB_S
                                         + wn * 32 + nt * 16 + bt_c) * 2);
            #pragma unroll
            for (int mt = 0; mt < 4; mt++)
                #pragma unroll
                for (int nt = 0; nt < 2; nt++) {
                    mma16816(acc[mt][nt * 2],     a[mt], &bb[nt][0]);
                    mma16816(acc[mt][nt * 2 + 1], a[mt], &bb[nt][2]);
                }
        }
    }

    const int emb = m0 + wm * 64 + (lane >> 2);
    const int enb = n0 + wn * 32 + (lane & 3) * 2;
    #pragma unroll
    for (int mt = 0; mt < 4; mt++) {
        #pragma unroll
        for (int nf = 0; nf < 4; nf++) {
            const int en = enb + nf * 8;
            const int em0 = emb + mt * 16;
            float v0 = acc[mt][nf][0], v1 = acc[mt][nf][1];
            float v2 = acc[mt][nf][2], v3 = acc[mt][nf][3];
            if (MODE == 0) {
                float b0 = bias[en], b1 = bias[en + 1];
                *(float2*)(C + (size_t)em0 * N + en)       = make_float2(v0 + b0, v1 + b1);
                *(float2*)(C + (size_t)(em0 + 8) * N + en) = make_float2(v2 + b0, v3 + b1);
            } else {
                *(uint32_t*)(Ch + (size_t)em0 * N + en)       = pack_h2(v0, v1);
                *(uint32_t*)(Ch + (size_t)(em0 + 8) * N + en) = pack_h2(v2, v3);
            }
        }
    }
}

// ---------------------------------------------------------------------------
// Tensorized causal flash attention (fp16 mma, fp32 acc).
// S = Q K^T (4 steps); O += P V (4 steps). 3-stage KV cp.async ring.
// Fully-masked warp-tiles skipped. Long blocks scheduled first.
// Epilogue writes fp16 proj input (g_ah, stride CH).
// ---------------------------------------------------------------------------
#define LDK 72
#define QS_HALVES (128 * LDK)              // 9216
#define KVSTG_HALVES (2 * 64 * LDK)        // 9216
#define AT_BYTES ((QS_HALVES + 3 * KVSTG_HALVES) * 2)   // 73728

__global__ __launch_bounds__(256, 2)
void flash_attn_mma(const __half* __restrict__ qh, __half* __restrict__ ah)
{
    extern __shared__ __align__(128) __half hsm[];
    const uint32_t sQ = smem_u32(hsm);

    const int tid  = threadIdx.x;
    const int lane = tid & 31;
    const int warp = tid >> 5;
    const int bh = blockIdx.y;
    const int b  = bh >> 4;
    const int h  = bh & 15;
    const int m0 = ((int)gridDim.x - 1 - (int)blockIdx.x) * 128;  // long first

    const __half* Qh = qh + (size_t)b * SEQ * QKV_C + h * HDIM;
    const __half* Kh = Qh + CH;
    const __half* Vh = Qh + 2 * CH;

    auto kv_stage = [&](int s) -> uint32_t {
        return sQ + (uint32_t)(QS_HALVES + s * KVSTG_HALVES) * 2;
    };
    auto load_kv = [&](int t, int s) {
        const uint32_t sK = kv_stage(s);
        const uint32_t sV = sK + (uint32_t)(64 * LDK) * 2;
        #pragma unroll
        for (int i = 0; i < 2; i++) {
            int c = tid + i * 256;
            int r = c >> 3, j = (c & 7) * 8;
            size_t g = (size_t)(t * 64 + r) * QKV_C + j;
            CP_ASYNC16(sK + (uint32_t)(r * LDK + j) * 2, Kh + g);
            CP_ASYNC16(sV + (uint32_t)(r * LDK + j) * 2, Vh + g);
        }
    };

    #pragma unroll
    for (int i = 0; i < 4; i++) {
        int c = tid + i * 256;                // 0..1023
        int r = c >> 3, j = (c & 7) * 8;
        CP_ASYNC16(sQ + (uint32_t)(r * LDK + j) * 2,
                   Qh + (size_t)(m0 + r) * QKV_C + j);
    }
    load_kv(0, 0); CP_COMMIT();
    load_kv(1, 1); CP_COMMIT();

    const int lmat = lane >> 3;
    const int lrow = lane & 7;
    const int a_row = warp * 16 + ((lmat & 1) << 3) + lrow;
    const int a_k   = (lmat >> 1) << 3;
    const int bs_rb = ((lmat >> 1) << 3) + lrow;
    const int bs_k  = (lmat & 1) << 3;
    const int bv_r  = ((lmat & 1) << 3) + lrow;
    const int bv_c  = (lmat >> 1) << 3;

    float m_i[2] = {-1e30f, -1e30f};
    float l_i[2] = {0.0f, 0.0f};
    float oacc[8][4];
    #pragma unroll
    for (int nf = 0; nf < 8; nf++)
        #pragma unroll
        for (int q = 0; q < 4; q++) oacc[nf][q] = 0.0f;

    const int r0 = m0 + warp * 16 + (lane >> 2);
    const int r1 = r0 + 8;
    const int wmin = m0 + warp * 16;         // first q row owned by this warp
    const int wmax = wmin + 15;              // last q row owned by this warp

    const int ntiles = (m0 >> 6) + 2;
    for (int t = 0; t < ntiles; t++) {
        const int k0 = t << 6;
        CP_WAIT1();
        __syncthreads();
        if (t + 2 < ntiles) load_kv(t + 2, (t + 2) % 3);
        CP_COMMIT();

        if (k0 > wmax) continue;   // tile fully masked for this warp

        const uint32_t sK = kv_stage(t % 3);
        const uint32_t sV = sK + (uint32_t)(64 * LDK) * 2;

        // ---- S = Q K^T : 4 k16 steps ----
        float sacc[8][4];
        #pragma unroll
        for (int nf = 0; nf < 8; nf++)
            #pragma unroll
            for (int q = 0; q < 4; q++) sacc[nf][q] = 0.0f;

        #pragma unroll
        for (int s = 0; s < 4; s++) {
            const int kb = s * 16;
            uint32_t a[4];
            ldsm_x4(a[0], a[1], a[2], a[3],
                    sQ + (uint32_t)(a_row * LDK + kb + a_k) * 2);
            #pragma unroll
            for (int nt = 0; nt < 4; nt++) {
                uint32_t bb[4];
                ldsm_x4(bb[0], bb[1], bb[2], bb[3],
                        sK + (uint32_t)((nt * 16 + bs_rb) * LDK + kb + bs_k) * 2);
                mma16816(sacc[nt * 2],     a, &bb[0]);
                mma16816(sacc[nt * 2 + 1], a, &bb[2]);
            }
        }

        // ---- online softmax ----
        // Mask needed if any key in tile can exceed any row of this warp:
        // compare against the warp's FIRST row (R14 bug: compared to last row).
        const bool need_mask = (k0 + 63 > wmin);
        float mx0 = -1e30f, mx1 = -1e30f;
        #pragma unroll
        for (int nf = 0; nf < 8; nf++) {
            const int cb = k0 + nf * 8 + ((lane & 3) << 1);
            float v0 = sacc[nf][0] * 0.125f;
            float v1 = sacc[nf][1] * 0.125f;
            float v2 = sacc[nf][2] * 0.125f;
            float v3 = sacc[nf][3] * 0.125f;
            if (need_mask) {
                if (cb     > r0) v0 = -1e30f;
                if (cb + 1 > r0) v1 = -1e30f;
                if (cb     > r1) v2 = -1e30f;
                if (cb + 1 > r1) v3 = -1e30f;
            }
            sacc[nf][0] = v0; sacc[nf][1] = v1;
            sacc[nf][2] = v2; sacc[nf][3] = v3;
            mx0 = fmaxf(mx0, fmaxf(v0, v1));
            mx1 = fmaxf(mx1, fmaxf(v2, v3));
        }
        mx0 = fmaxf(mx0, __shfl_xor_sync(0xffffffffu, mx0, 1));
        mx0 = fmaxf(mx0, __shfl_xor_sync(0xffffffffu, mx0, 2));
        mx1 = fmaxf(mx1, __shfl_xor_sync(0xffffffffu, mx1, 1));
        mx1 = fmaxf(mx1, __shfl_xor_sync(0xffffffffu, mx1, 2));

        const float mn0 = fmaxf(m_i[0], mx0);
        const float mn1 = fmaxf(m_i[1], mx1);
        const float cr0 = __expf(m_i[0] - mn0);
        const float cr1 = __expf(m_i[1] - mn1);
        m_i[0] = mn0; m_i[1] = mn1;

        float sm0 = 0.f, sm1 = 0.f;
        #pragma unroll
        for (int nf = 0; nf < 8; nf++) {
            float p0 = __expf(sacc[nf][0] - mn0);
            float p1 = __expf(sacc[nf][1] - mn0);
            float p2 = __expf(sacc[nf][2] - mn1);
            float p3 = __expf(sacc[nf][3] - mn1);
            sacc[nf][0] = p0; sacc[nf][1] = p1;
            sacc[nf][2] = p2; sacc[nf][3] = p3;
            sm0 += p0 + p1;  sm1 += p2 + p3;
        }
        sm0 += __shfl_xor_sync(0xffffffffu, sm0, 1);
        sm0 += __shfl_xor_sync(0xffffffffu, sm0, 2);
        sm1 += __shfl_xor_sync(0xffffffffu, sm1, 1);
        sm1 += __shfl_xor_sync(0xffffffffu, sm1, 2);
        l_i[0] = l_i[0] * cr0 + sm0;
        l_i[1] = l_i[1] * cr1 + sm1;
        #pragma unroll
        for (int nf = 0; nf < 8; nf++) {
            oacc[nf][0] *= cr0; oacc[nf][1] *= cr0;
            oacc[nf][2] *= cr1; oacc[nf][3] *= cr1;
        }

        // ---- O += P V : 4 k16 steps ----
        #pragma unroll
        for (int s = 0; s < 4; s++) {
            const int kb = s * 16;
            uint32_t pa[4];
            pa[0] = pack_h2(sacc[2 * s][0],     sacc[2 * s][1]);
            pa[1] = pack_h2(sacc[2 * s][2],     sacc[2 * s][3]);
            pa[2] = pack_h2(sacc[2 * s + 1][0], sacc[2 * s + 1][1]);
            pa[3] = pack_h2(sacc[2 * s + 1][2], sacc[2 * s + 1][3]);
            #pragma unroll
            for (int nt = 0; nt < 4; nt++) {
                uint32_t bb[4];
                ldsm_x4t(bb[0], bb[1], bb[2], bb[3],
                         sV + (uint32_t)((kb + bv_r) * LDK + nt * 16 + bv_c) * 2);
                mma16816(oacc[nt * 2],     pa, &bb[0]);
                mma16816(oacc[nt * 2 + 1], pa, &bb[2]);
            }
        }
    }

    // ---- epilogue: normalize + fp16 write to g_ah ----
    const float inv0 = 1.0f / l_i[0];
    const float inv1 = 1.0f / l_i[1];
    const size_t row0 = (size_t)(b * SEQ + r0) * CH;
    const size_t row1 = (size_t)(b * SEQ + r1) * CH;
    #pragma unroll
    for (int nf = 0; nf < 8; nf++) {
        const int col = h * HDIM + nf * 8 + ((lane & 3) << 1);
        *(uint32_t*)(ah + row0 + col) = pack_h2(oacc[nf][0] * inv0,
                                                oacc[nf][1] * inv0);
        *(uint32_t*)(ah + row1 + col) = pack_h2(oacc[nf][2] * inv1,
                                                oacc[nf][3] * inv1);
    }
}

// ---------------------------------------------------------------------------
extern "C" void kernel_launch(void* const* d_in, const int* in_sizes, int n_in,
                              void* d_out, int out_size)
{
    const float* x     = (const float*)d_in[0];
    const float* Wqkv  = (const float*)d_in[2];
    const float* Wproj = (const float*)d_in[3];
    const float* bproj = (const float*)d_in[4];
    float* out = (float*)d_out;

    void *p_qh, *p_xh, *p_ah, *p_wq, *p_wp;
    cudaGetSymbolAddress(&p_qh, g_qh);
    cudaGetSymbolAddress(&p_xh, g_xh);
    cudaGetSymbolAddress(&p_ah, g_ah);
    cudaGetSymbolAddress(&p_wq, g_wq16);
    cudaGetSymbolAddress(&p_wp, g_wp16);
    __half* qh   = (__half*)p_qh;
    __half* xh   = (__half*)p_xh;
    __half* ah   = (__half*)p_ah;
    __half* wq16 = (__half*)p_wq;
    __half* wp16 = (__half*)p_wp;

    cudaFuncSetAttribute(gemm_mma<0>, cudaFuncAttributeMaxDynamicSharedMemorySize,
                         GSM_BYTES);
    cudaFuncSetAttribute(gemm_mma<1>, cudaFuncAttributeMaxDynamicSharedMemorySize,
                         GSM_BYTES);
    cudaFuncSetAttribute(flash_attn_mma, cudaFuncAttributeMaxDynamicSharedMemorySize,
                         AT_BYTES);

    // conversions (flat rounds; layouts preserved)
    round_flat<<<(ROWS * CH / 4 + 255) / 256, 256>>>(x, xh, ROWS * CH / 4);
    round_flat<<<(CH * QKV_C / 4 + 255) / 256, 256>>>(Wqkv, wq16, CH * QKV_C / 4);
    round_flat<<<(CH * CH / 4 + 255) / 256, 256>>>(Wproj, wp16, CH * CH / 4);

    // 1) qkv = x @ Wqkv   (K=1024)
    dim3 g1(QKV_C / 128, ROWS / 128);
    gemm_mma<1><<<g1, 256, GSM_BYTES>>>(xh, CH, wq16, nullptr, nullptr,
                                        qh, QKV_C, CH / BK);

    // 2) causal flash attention -> fp16 proj input
    dim3 g2(SEQ / 128, BATCH * HEADS);
    flash_attn_mma<<<g2, 256, AT_BYTES>>>(qh, ah);

    // 3) out = attn @ Wproj + b   (K=1024)
    dim3 g3(CH / 128, ROWS / 128);
    gemm_mma<0><<<g3, 256, GSM_BYTES>>>(ah, CH, wp16, bproj, out,
                                        nullptr, CH, CH / BK);
}

// round 16
// speedup vs baseline: 1.0136x; 1.0136x over previous
#include <cuda_runtime.h>
#include <cuda_fp16.h>
#include <cstdint>

// ---------------------------------------------------------------------------
// AttentionRAR: x -> qkv GEMM -> causal flash attention -> proj GEMM (+bias)
// B=4, N=2048, C=1024, H=16, D=64
// All matmuls pure-fp16 mma.sync, fp32 accumulate.
// GEMMs: row-major A x row-major B^T (non-trans ldmatrix; R13-proven path).
// Attention: R15 (fixed causal mask, warp skip, fp16 in/out).
// ---------------------------------------------------------------------------

#define BATCH 4
#define SEQ   2048
#define CH    1024
#define HEADS 16
#define HDIM  64
#define ROWS  (BATCH * SEQ)       // 8192
#define QKV_C (3 * CH)            // 3072

// Scratch
__device__ __align__(1024) __half g_qh [(size_t)ROWS * QKV_C];  // qkv (fp16)
__device__ __align__(1024) __half g_xh [(size_t)ROWS * CH];     // x (fp16)
__device__ __align__(1024) __half g_ah [(size_t)ROWS * CH];     // attn out (fp16)
__device__ __align__(1024) __half g_wqkt[(size_t)QKV_C * CH];   // Wqkv^T fp16
__device__ __align__(1024) __half g_wpt [(size_t)CH * CH];      // Wproj^T fp16

// ======================= helpers ===========================================
__device__ __forceinline__ uint32_t smem_u32(const void* p) {
    uint32_t a;
    asm("{ .reg .u64 t; cvta.to.shared.u64 t, %1; cvt.u32.u64 %0, t; }"
        : "=r"(a) : "l"(p));
    return a;
}

#define CP_ASYNC16(sm, gp) \
    asm volatile("cp.async.cg.shared.global [%0], [%1], 16;" :: "r"(sm), "l"(gp))
#define CP_COMMIT() asm volatile("cp.async.commit_group;" ::: "memory")
#define CP_WAIT1()  asm volatile("cp.async.wait_group 1;" ::: "memory")

__device__ __forceinline__ void ldsm_x4(uint32_t& r0, uint32_t& r1,
                                        uint32_t& r2, uint32_t& r3, uint32_t a) {
    asm volatile("ldmatrix.sync.aligned.m8n8.x4.shared.b16 {%0,%1,%2,%3}, [%4];"
                 : "=r"(r0), "=r"(r1), "=r"(r2), "=r"(r3) : "r"(a));
}
__device__ __forceinline__ void ldsm_x4t(uint32_t& r0, uint32_t& r1,
                                         uint32_t& r2, uint32_t& r3, uint32_t a) {
    asm volatile("ldmatrix.sync.aligned.m8n8.x4.trans.shared.b16 {%0,%1,%2,%3}, [%4];"
                 : "=r"(r0), "=r"(r1), "=r"(r2), "=r"(r3) : "r"(a));
}
__device__ __forceinline__ void mma16816(float* c, const uint32_t* a,
                                         const uint32_t* b) {
    asm volatile("mma.sync.aligned.m16n8k16.row.col.f32.f16.f16.f32 "
                 "{%0,%1,%2,%3}, {%4,%5,%6,%7}, {%8,%9}, {%0,%1,%2,%3};"
                 : "+f"(c[0]), "+f"(c[1]), "+f"(c[2]), "+f"(c[3])
                 : "r"(a[0]), "r"(a[1]), "r"(a[2]), "r"(a[3]),
                   "r"(b[0]), "r"(b[1]));
}
__device__ __forceinline__ uint32_t pack_h2(float a, float b) {
    __half2 h = __floats2half2_rn(a, b);
    return *(uint32_t*)&h;
}

// ---------------------------------------------------------------------------
// Conversions
// ---------------------------------------------------------------------------
__global__ void round_flat(const float* __restrict__ in, __half* __restrict__ out,
                           int n4)
{
    int i = blockIdx.x * blockDim.x + threadIdx.x;
    if (i < n4) {
        float4 v = ((const float4*)in)[i];
        uint32_t lo = pack_h2(v.x, v.y);
        uint32_t hi = pack_h2(v.z, v.w);
        ((uint2*)out)[i] = make_uint2(lo, hi);
    }
}

// W [CH, N] fp32 -> Wt [N, CH] fp16 (transpose + round)
__global__ void roundT(const float* __restrict__ W, __half* __restrict__ Wt, int N)
{
    __shared__ float t[32][33];
    int n0 = blockIdx.x * 32, k0 = blockIdx.y * 32;
    int tx = threadIdx.x, ty = threadIdx.y;   // 32 x 8
    #pragma unroll
    for (int j = 0; j < 32; j += 8)
        t[ty + j][tx] = W[(size_t)(k0 + ty + j) * N + n0 + tx];
    __syncthreads();
    #pragma unroll
    for (int j = 0; j < 32; j += 8)
        Wt[(size_t)(n0 + ty + j) * CH + k0 + tx] = __float2half(t[tx][ty + j]);
}

// ---------------------------------------------------------------------------
// mma.sync fp16 GEMM, fp32 acc: C[M,N] = A[M,K] * Bt[N,K]^T (+bias)
// Row-major A and Bt; non-trans ldmatrix both (R13-proven, 44.7% tensor).
// 128x128 CTA tile, BK=32, 8 warps (2x4), warp tile 64x32, 3-stage ring.
// MODE 0: fp32 out + bias. MODE 1: fp16 out.
// ---------------------------------------------------------------------------
#define BK   32
#define LDSW 40
#define ASTG (128 * LDSW * 2)       // 10240 B per stage per operand
#define NSTG 3
#define GSM_BYTES (2 * NSTG * ASTG) // 61440

template<int MODE>
__global__ __launch_bounds__(256)
void gemm_mma(const __half* __restrict__ A, int lda,
              const __half* __restrict__ Bt, int ldb,
              const float* __restrict__ bias, float* __restrict__ C,
              __half* __restrict__ Ch, int N, int nchunk)
{
    extern __shared__ __align__(128) char gsm[];
    const uint32_t sb = smem_u32(gsm);

    const int tid  = threadIdx.x;
    const int lane = tid & 31;
    const int warp = tid >> 5;
    const int wm   = warp >> 2;      // 0..1
    const int wn   = warp & 3;       // 0..3
    const int m0   = blockIdx.y * 128;
    const int n0   = blockIdx.x * 128;

    const int crow = tid >> 2;
    const int ckp  = (tid & 3) * 8;
    const uint32_t so0 = (uint32_t)(crow * LDSW + ckp) * 2;
    const uint32_t so1 = (uint32_t)((crow + 64) * LDSW + ckp) * 2;

    auto load = [&](int kc, int buf) {
        const uint32_t sA = sb + buf * ASTG;
        const uint32_t sB = sb + NSTG * ASTG + buf * ASTG;
        const __half* Ag = A + (size_t)(m0 + crow) * lda + kc * BK + ckp;
        const __half* Bg = Bt + (size_t)(n0 + crow) * ldb + kc * BK + ckp;
        CP_ASYNC16(sA + so0, Ag);
        CP_ASYNC16(sA + so1, Ag + (size_t)64 * lda);
        CP_ASYNC16(sB + so0, Bg);
        CP_ASYNC16(sB + so1, Bg + (size_t)64 * ldb);
    };

    const int lmat = lane >> 3;
    const int lrow = lane & 7;
    const int a_row_base = wm * 64 + ((lmat & 1) << 3) + lrow;
    const int a_k_off    = (lmat >> 1) << 3;
    const int b_row_base = wn * 32 + ((lmat >> 1) << 3) + lrow;
    const int b_k_off    = (lmat & 1) << 3;

    float acc[4][4][4];
    #pragma unroll
    for (int i = 0; i < 4; i++)
        #pragma unroll
        for (int j = 0; j < 4; j++)
            #pragma unroll
            for (int q = 0; q < 4; q++) acc[i][j][q] = 0.0f;

    load(0, 0); CP_COMMIT();
    load(1, 1); CP_COMMIT();

    for (int t = 0; t < nchunk; t++) {
        const int buf = t % NSTG;
        CP_WAIT1();
        __syncthreads();
        if (t + 2 < nchunk) load(t + 2, (t + 2) % NSTG);
        CP_COMMIT();

        const uint32_t sA = sb + buf * ASTG;
        const uint32_t sB = sb + NSTG * ASTG + buf * ASTG;
        #pragma unroll
        for (int ks = 0; ks < 2; ks++) {
            uint32_t a[4][4];
            #pragma unroll
            for (int mt = 0; mt < 4; mt++)
                ldsm_x4(a[mt][0], a[mt][1], a[mt][2], a[mt][3],
                        sA + (uint32_t)((a_row_base + mt * 16) * LDSW
                                        + ks * 16 + a_k_off) * 2);
            uint32_t b[2][4];
            #pragma unroll
            for (int jj = 0; jj < 2; jj++)
                ldsm_x4(b[jj][0], b[jj][1], b[jj][2], b[jj][3],
                        sB + (uint32_t)((b_row_base + jj * 16) * LDSW
                                        + ks * 16 + b_k_off) * 2);
            #pragma unroll
            for (int mt = 0; mt < 4; mt++)
                #pragma unroll
                for (int nf = 0; nf < 4; nf++)
                    mma16816(acc[mt][nf], a[mt], &b[nf >> 1][(nf & 1) * 2]);
        }
    }

    const int emb = m0 + wm * 64 + (lane >> 2);
    const int enb = n0 + wn * 32 + (lane & 3) * 2;
    #pragma unroll
    for (int mt = 0; mt < 4; mt++) {
        #pragma unroll
        for (int nf = 0; nf < 4; nf++) {
            const int en = enb + nf * 8;
            const int em0 = emb + mt * 16;
            float v0 = acc[mt][nf][0], v1 = acc[mt][nf][1];
            float v2 = acc[mt][nf][2], v3 = acc[mt][nf][3];
            if (MODE == 0) {
                float b0 = bias[en], b1 = bias[en + 1];
                *(float2*)(C + (size_t)em0 * N + en)       = make_float2(v0 + b0, v1 + b1);
                *(float2*)(C + (size_t)(em0 + 8) * N + en) = make_float2(v2 + b0, v3 + b1);
            } else {
                *(uint32_t*)(Ch + (size_t)em0 * N + en)       = pack_h2(v0, v1);
                *(uint32_t*)(Ch + (size_t)(em0 + 8) * N + en) = pack_h2(v2, v3);
            }
        }
    }
}

// ---------------------------------------------------------------------------
// Tensorized causal flash attention (fp16 mma, fp32 acc) — R15 verbatim.
// S = Q K^T (4 steps); O += P V (4 steps). 3-stage KV cp.async ring.
// Fully-masked warp-tiles skipped. Long blocks scheduled first.
// ---------------------------------------------------------------------------
#define LDK 72
#define QS_HALVES (128 * LDK)              // 9216
#define KVSTG_HALVES (2 * 64 * LDK)        // 9216
#define AT_BYTES ((QS_HALVES + 3 * KVSTG_HALVES) * 2)   // 73728

__global__ __launch_bounds__(256, 2)
void flash_attn_mma(const __half* __restrict__ qh, __half* __restrict__ ah)
{
    extern __shared__ __align__(128) __half hsm[];
    const uint32_t sQ = smem_u32(hsm);

    const int tid  = threadIdx.x;
    const int lane = tid & 31;
    const int warp = tid >> 5;
    const int bh = blockIdx.y;
    const int b  = bh >> 4;
    const int h  = bh & 15;
    const int m0 = ((int)gridDim.x - 1 - (int)blockIdx.x) * 128;  // long first

    const __half* Qh = qh + (size_t)b * SEQ * QKV_C + h * HDIM;
    const __half* Kh = Qh + CH;
    const __half* Vh = Qh + 2 * CH;

    auto kv_stage = [&](int s) -> uint32_t {
        return sQ + (uint32_t)(QS_HALVES + s * KVSTG_HALVES) * 2;
    };
    auto load_kv = [&](int t, int s) {
        const uint32_t sK = kv_stage(s);
        const uint32_t sV = sK + (uint32_t)(64 * LDK) * 2;
        #pragma unroll
        for (int i = 0; i < 2; i++) {
            int c = tid + i * 256;
            int r = c >> 3, j = (c & 7) * 8;
            size_t g = (size_t)(t * 64 + r) * QKV_C + j;
            CP_ASYNC16(sK + (uint32_t)(r * LDK + j) * 2, Kh + g);
            CP_ASYNC16(sV + (uint32_t)(r * LDK + j) * 2, Vh + g);
        }
    };

    #pragma unroll
    for (int i = 0; i < 4; i++) {
        int c = tid + i * 256;                // 0..1023
        int r = c >> 3, j = (c & 7) * 8;
        CP_ASYNC16(sQ + (uint32_t)(r * LDK + j) * 2,
                   Qh + (size_t)(m0 + r) * QKV_C + j);
    }
    load_kv(0, 0); CP_COMMIT();
    load_kv(1, 1); CP_COMMIT();

    const int lmat = lane >> 3;
    const int lrow = lane & 7;
    const int a_row = warp * 16 + ((lmat & 1) << 3) + lrow;
    const int a_k   = (lmat >> 1) << 3;
    const int bs_rb = ((lmat >> 1) << 3) + lrow;
    const int bs_k  = (lmat & 1) << 3;
    const int bv_r  = ((lmat & 1) << 3) + lrow;
    const int bv_c  = (lmat >> 1) << 3;

    float m_i[2] = {-1e30f, -1e30f};
    float l_i[2] = {0.0f, 0.0f};
    float oacc[8][4];
    #pragma unroll
    for (int nf = 0; nf < 8; nf++)
        #pragma unroll
        for (int q = 0; q < 4; q++) oacc[nf][q] = 0.0f;

    const int r0 = m0 + warp * 16 + (lane >> 2);
    const int r1 = r0 + 8;
    const int wmin = m0 + warp * 16;
    const int wmax = wmin + 15;

    const int ntiles = (m0 >> 6) + 2;
    for (int t = 0; t < ntiles; t++) {
        const int k0 = t << 6;
        CP_WAIT1();
        __syncthreads();
        if (t + 2 < ntiles) load_kv(t + 2, (t + 2) % 3);
        CP_COMMIT();

        if (k0 > wmax) continue;   // tile fully masked for this warp

        const uint32_t sK = kv_stage(t % 3);
        const uint32_t sV = sK + (uint32_t)(64 * LDK) * 2;

        // ---- S = Q K^T : 4 k16 steps ----
        float sacc[8][4];
        #pragma unroll
        for (int nf = 0; nf < 8; nf++)
            #pragma unroll
            for (int q = 0; q < 4; q++) sacc[nf][q] = 0.0f;

        #pragma unroll
        for (int s = 0; s < 4; s++) {
            const int kb = s * 16;
            uint32_t a[4];
            ldsm_x4(a[0], a[1], a[2], a[3],
                    sQ + (uint32_t)(a_row * LDK + kb + a_k) * 2);
            #pragma unroll
            for (int nt = 0; nt < 4; nt++) {
                uint32_t bb[4];
                ldsm_x4(bb[0], bb[1], bb[2], bb[3],
                        sK + (uint32_t)((nt * 16 + bs_rb) * LDK + kb + bs_k) * 2);
                mma16816(sacc[nt * 2],     a, &bb[0]);
                mma16816(sacc[nt * 2 + 1], a, &bb[2]);
            }
        }

        // ---- online softmax (mask vs warp's FIRST row) ----
        const bool need_mask = (k0 + 63 > wmin);
        float mx0 = -1e30f, mx1 = -1e30f;
        #pragma unroll
        for (int nf = 0; nf < 8; nf++) {
            const int cb = k0 + nf * 8 + ((lane & 3) << 1);
            float v0 = sacc[nf][0] * 0.125f;
            float v1 = sacc[nf][1] * 0.125f;
            float v2 = sacc[nf][2] * 0.125f;
            float v3 = sacc[nf][3] * 0.125f;
            if (need_mask) {
                if (cb     > r0) v0 = -1e30f;
                if (cb + 1 > r0) v1 = -1e30f;
                if (cb     > r1) v2 = -1e30f;
                if (cb + 1 > r1) v3 = -1e30f;
            }
            sacc[nf][0] = v0; sacc[nf][1] = v1;
            sacc[nf][2] = v2; sacc[nf][3] = v3;
            mx0 = fmaxf(mx0, fmaxf(v0, v1));
            mx1 = fmaxf(mx1, fmaxf(v2, v3));
        }
        mx0 = fmaxf(mx0, __shfl_xor_sync(0xffffffffu, mx0, 1));
        mx0 = fmaxf(mx0, __shfl_xor_sync(0xffffffffu, mx0, 2));
        mx1 = fmaxf(mx1, __shfl_xor_sync(0xffffffffu, mx1, 1));
        mx1 = fmaxf(mx1, __shfl_xor_sync(0xffffffffu, mx1, 2));

        const float mn0 = fmaxf(m_i[0], mx0);
        const float mn1 = fmaxf(m_i[1], mx1);
        const float cr0 = __expf(m_i[0] - mn0);
        const float cr1 = __expf(m_i[1] - mn1);
        m_i[0] = mn0; m_i[1] = mn1;

        float sm0 = 0.f, sm1 = 0.f;
        #pragma unroll
        for (int nf = 0; nf < 8; nf++) {
            float p0 = __expf(sacc[nf][0] - mn0);
            float p1 = __expf(sacc[nf][1] - mn0);
            float p2 = __expf(sacc[nf][2] - mn1);
            float p3 = __expf(sacc[nf][3] - mn1);
            sacc[nf][0] = p0; sacc[nf][1] = p1;
            sacc[nf][2] = p2; sacc[nf][3] = p3;
            sm0 += p0 + p1;  sm1 += p2 + p3;
        }
        sm0 += __shfl_xor_sync(0xffffffffu, sm0, 1);
        sm0 += __shfl_xor_sync(0xffffffffu, sm0, 2);
        sm1 += __shfl_xor_sync(0xffffffffu, sm1, 1);
        sm1 += __shfl_xor_sync(0xffffffffu, sm1, 2);
        l_i[0] = l_i[0] * cr0 + sm0;
        l_i[1] = l_i[1] * cr1 + sm1;
        #pragma unroll
        for (int nf = 0; nf < 8; nf++) {
            oacc[nf][0] *= cr0; oacc[nf][1] *= cr0;
            oacc[nf][2] *= cr1; oacc[nf][3] *= cr1;
        }

        // ---- O += P V : 4 k16 steps ----
        #pragma unroll
        for (int s = 0; s < 4; s++) {
            const int kb = s * 16;
            uint32_t pa[4];
            pa[0] = pack_h2(sacc[2 * s][0],     sacc[2 * s][1]);
            pa[1] = pack_h2(sacc[2 * s][2],     sacc[2 * s][3]);
            pa[2] = pack_h2(sacc[2 * s + 1][0], sacc[2 * s + 1][1]);
            pa[3] = pack_h2(sacc[2 * s + 1][2], sacc[2 * s + 1][3]);
            #pragma unroll
            for (int nt = 0; nt < 4; nt++) {
                uint32_t bb[4];
                ldsm_x4t(bb[0], bb[1], bb[2], bb[3],
                         sV + (uint32_t)((kb + bv_r) * LDK + nt * 16 + bv_c) * 2);
                mma16816(oacc[nt * 2],     pa, &bb[0]);
                mma16816(oacc[nt * 2 + 1], pa, &bb[2]);
            }
        }
    }

    // ---- epilogue: normalize + fp16 write to g_ah ----
    const float inv0 = 1.0f / l_i[0];
    const float inv1 = 1.0f / l_i[1];
    const size_t row0 = (size_t)(b * SEQ + r0) * CH;
    const size_t row1 = (size_t)(b * SEQ + r1) * CH;
    #pragma unroll
    for (int nf = 0; nf < 8; nf++) {
        const int col = h * HDIM + nf * 8 + ((lane & 3) << 1);
        *(uint32_t*)(ah + row0 + col) = pack_h2(oacc[nf][0] * inv0,
                                                oacc[nf][1] * inv0);
        *(uint32_t*)(ah + row1 + col) = pack_h2(oacc[nf][2] * inv1,
                                                oacc[nf][3] * inv1);
    }
}

// ---------------------------------------------------------------------------
extern "C" void kernel_launch(void* const* d_in, const int* in_sizes, int n_in,
                              void* d_out, int out_size)
{
    const float* x     = (const float*)d_in[0];
    const float* Wqkv  = (const float*)d_in[2];
    const float* Wproj = (const float*)d_in[3];
    const float* bproj = (const float*)d_in[4];
    float* out = (float*)d_out;

    void *p_qh, *p_xh, *p_ah, *p_wq, *p_wp;
    cudaGetSymbolAddress(&p_qh, g_qh);
    cudaGetSymbolAddress(&p_xh, g_xh);
    cudaGetSymbolAddress(&p_ah, g_ah);
    cudaGetSymbolAddress(&p_wq, g_wqkt);
    cudaGetSymbolAddress(&p_wp, g_wpt);
    __half* qh   = (__half*)p_qh;
    __half* xh   = (__half*)p_xh;
    __half* ah   = (__half*)p_ah;
    __half* wqkt = (__half*)p_wq;
    __half* wpt  = (__half*)p_wp;

    cudaFuncSetAttribute(gemm_mma<0>, cudaFuncAttributeMaxDynamicSharedMemorySize,
                         GSM_BYTES);
    cudaFuncSetAttribute(gemm_mma<1>, cudaFuncAttributeMaxDynamicSharedMemorySize,
                         GSM_BYTES);
    cudaFuncSetAttribute(flash_attn_mma, cudaFuncAttributeMaxDynamicSharedMemorySize,
                         AT_BYTES);

    // conversions
    round_flat<<<(ROWS * CH / 4 + 255) / 256, 256>>>(x, xh, ROWS * CH / 4);
    dim3 wt1(QKV_C / 32, CH / 32);
    roundT<<<wt1, dim3(32, 8)>>>(Wqkv, wqkt, QKV_C);
    dim3 wt2(CH / 32, CH / 32);
    roundT<<<wt2, dim3(32, 8)>>>(Wproj, wpt, CH);

    // 1) qkv = x @ Wqkv   (K=1024)
    dim3 g1(QKV_C / 128, ROWS / 128);
    gemm_mma<1><<<g1, 256, GSM_BYTES>>>(xh, CH, wqkt, CH, nullptr, nullptr,
                                        qh, QKV_C, CH / BK);

    // 2) causal flash attention -> fp16 proj input
    dim3 g2(SEQ / 128, BATCH * HEADS);
    flash_attn_mma<<<g2, 256, AT_BYTES>>>(qh, ah);

    // 3) out = attn @ Wproj + b   (K=1024)
    dim3 g3(CH / 128, ROWS / 128);
    gemm_mma<0><<<g3, 256, GSM_BYTES>>>(ah, CH, wpt, CH, bproj, out,
                                        nullptr, CH, CH / BK);
}

// round 17
// speedup vs baseline: 1.7251x; 1.7020x over previous
#include <cuda_runtime.h>
#include <cuda_fp16.h>
#include <cstdint>

// ---------------------------------------------------------------------------
// AttentionRAR: x -> qkv GEMM -> causal flash attention -> proj GEMM (+bias)
// B=4, N=2048, C=1024, H=16, D=64
// All matmuls pure-fp16 mma.sync, fp32 accumulate.
// GEMMs: row-major A x row-major B^T, non-trans ldmatrix, BK=64, 3-stage ring.
// Attention: R16 verbatim (fixed causal mask, warp skip, fp16 in/out).
// ---------------------------------------------------------------------------

#define BATCH 4
#define SEQ   2048
#define CH    1024
#define HEADS 16
#define HDIM  64
#define ROWS  (BATCH * SEQ)       // 8192
#define QKV_C (3 * CH)            // 3072

// Scratch
__device__ __align__(1024) __half g_qh [(size_t)ROWS * QKV_C];  // qkv (fp16)
__device__ __align__(1024) __half g_xh [(size_t)ROWS * CH];     // x (fp16)
__device__ __align__(1024) __half g_ah [(size_t)ROWS * CH];     // attn out (fp16)
__device__ __align__(1024) __half g_wqkt[(size_t)QKV_C * CH];   // Wqkv^T fp16
__device__ __align__(1024) __half g_wpt [(size_t)CH * CH];      // Wproj^T fp16

// ======================= helpers ===========================================
__device__ __forceinline__ uint32_t smem_u32(const void* p) {
    uint32_t a;
    asm("{ .reg .u64 t; cvta.to.shared.u64 t, %1; cvt.u32.u64 %0, t; }"
        : "=r"(a) : "l"(p));
    return a;
}

#define CP_ASYNC16(sm, gp) \
    asm volatile("cp.async.cg.shared.global [%0], [%1], 16;" :: "r"(sm), "l"(gp))
#define CP_COMMIT() asm volatile("cp.async.commit_group;" ::: "memory")
#define CP_WAIT1()  asm volatile("cp.async.wait_group 1;" ::: "memory")

__device__ __forceinline__ void ldsm_x4(uint32_t& r0, uint32_t& r1,
                                        uint32_t& r2, uint32_t& r3, uint32_t a) {
    asm volatile("ldmatrix.sync.aligned.m8n8.x4.shared.b16 {%0,%1,%2,%3}, [%4];"
                 : "=r"(r0), "=r"(r1), "=r"(r2), "=r"(r3) : "r"(a));
}
__device__ __forceinline__ void ldsm_x4t(uint32_t& r0, uint32_t& r1,
                                         uint32_t& r2, uint32_t& r3, uint32_t a) {
    asm volatile("ldmatrix.sync.aligned.m8n8.x4.trans.shared.b16 {%0,%1,%2,%3}, [%4];"
                 : "=r"(r0), "=r"(r1), "=r"(r2), "=r"(r3) : "r"(a));
}
__device__ __forceinline__ void mma16816(float* c, const uint32_t* a,
                                         const uint32_t* b) {
    asm volatile("mma.sync.aligned.m16n8k16.row.col.f32.f16.f16.f32 "
                 "{%0,%1,%2,%3}, {%4,%5,%6,%7}, {%8,%9}, {%0,%1,%2,%3};"
                 : "+f"(c[0]), "+f"(c[1]), "+f"(c[2]), "+f"(c[3])
                 : "r"(a[0]), "r"(a[1]), "r"(a[2]), "r"(a[3]),
                   "r"(b[0]), "r"(b[1]));
}
__device__ __forceinline__ uint32_t pack_h2(float a, float b) {
    __half2 h = __floats2half2_rn(a, b);
    return *(uint32_t*)&h;
}

// ---------------------------------------------------------------------------
// Conversions
// ---------------------------------------------------------------------------
__global__ void round_flat(const float* __restrict__ in, __half* __restrict__ out,
                           int n4)
{
    int i = blockIdx.x * blockDim.x + threadIdx.x;
    if (i < n4) {
        float4 v = ((const float4*)in)[i];
        uint32_t lo = pack_h2(v.x, v.y);
        uint32_t hi = pack_h2(v.z, v.w);
        ((uint2*)out)[i] = make_uint2(lo, hi);
    }
}

// W [CH, N] fp32 -> Wt [N, CH] fp16 (transpose + round)
__global__ void roundT(const float* __restrict__ W, __half* __restrict__ Wt, int N)
{
    __shared__ float t[32][33];
    int n0 = blockIdx.x * 32, k0 = blockIdx.y * 32;
    int tx = threadIdx.x, ty = threadIdx.y;   // 32 x 8
    #pragma unroll
    for (int j = 0; j < 32; j += 8)
        t[ty + j][tx] = W[(size_t)(k0 + ty + j) * N + n0 + tx];
    __syncthreads();
    #pragma unroll
    for (int j = 0; j < 32; j += 8)
        Wt[(size_t)(n0 + ty + j) * CH + k0 + tx] = __float2half(t[tx][ty + j]);
}

// ---------------------------------------------------------------------------
// mma.sync fp16 GEMM, fp32 acc: C[M,N] = A[M,K] * Bt[N,K]^T (+bias)
// Row-major A and Bt; non-trans ldmatrix both. BK=64 (half the syncs of BK=32).
// 128x128 CTA tile, 8 warps (2x4), warp tile 64x32, 3-stage cp.async ring.
// MODE 0: fp32 out + bias. MODE 1: fp16 out.
// ---------------------------------------------------------------------------
#define BK   64
#define LDSW 72                     // 64 + 8 pad (halves)
#define ASTG (128 * LDSW * 2)       // 18432 B per stage per operand
#define NSTG 3
#define GSM_BYTES (2 * NSTG * ASTG) // 110592

template<int MODE>
__global__ __launch_bounds__(256)
void gemm_mma(const __half* __restrict__ A, int lda,
              const __half* __restrict__ Bt, int ldb,
              const float* __restrict__ bias, float* __restrict__ C,
              __half* __restrict__ Ch, int N, int nchunk)
{
    extern __shared__ __align__(128) char gsm[];
    const uint32_t sb = smem_u32(gsm);

    const int tid  = threadIdx.x;
    const int lane = tid & 31;
    const int warp = tid >> 5;
    const int wm   = warp >> 2;      // 0..1
    const int wn   = warp & 3;       // 0..3
    const int m0   = blockIdx.y * 128;
    const int n0   = blockIdx.x * 128;

    // per-tile: 128 rows x 64 halves = 1024 x 16B chunks per operand
    auto load = [&](int kc, int buf) {
        const uint32_t sA = sb + buf * ASTG;
        const uint32_t sB = sb + NSTG * ASTG + buf * ASTG;
        #pragma unroll
        for (int i = 0; i < 4; i++) {
            int c = tid + i * 256;          // 0..1023
            int r = c >> 3, j = (c & 7) * 8;
            uint32_t so = (uint32_t)(r * LDSW + j) * 2;
            CP_ASYNC16(sA + so, A + (size_t)(m0 + r) * lda + kc * BK + j);
            CP_ASYNC16(sB + so, Bt + (size_t)(n0 + r) * ldb + kc * BK + j);
        }
    };

    const int lmat = lane >> 3;
    const int lrow = lane & 7;
    const int a_row_base = wm * 64 + ((lmat & 1) << 3) + lrow;
    const int a_k_off    = (lmat >> 1) << 3;
    const int b_row_base = wn * 32 + ((lmat >> 1) << 3) + lrow;
    const int b_k_off    = (lmat & 1) << 3;

    float acc[4][4][4];
    #pragma unroll
    for (int i = 0; i < 4; i++)
        #pragma unroll
        for (int j = 0; j < 4; j++)
            #pragma unroll
            for (int q = 0; q < 4; q++) acc[i][j][q] = 0.0f;

    load(0, 0); CP_COMMIT();
    load(1, 1); CP_COMMIT();

    for (int t = 0; t < nchunk; t++) {
        const int buf = t % NSTG;
        CP_WAIT1();
        __syncthreads();
        if (t + 2 < nchunk) load(t + 2, (t + 2) % NSTG);
        CP_COMMIT();

        const uint32_t sA = sb + buf * ASTG;
        const uint32_t sB = sb + NSTG * ASTG + buf * ASTG;
        #pragma unroll
        for (int ks = 0; ks < 4; ks++) {
            uint32_t a[4][4];
            #pragma unroll
            for (int mt = 0; mt < 4; mt++)
                ldsm_x4(a[mt][0], a[mt][1], a[mt][2], a[mt][3],
                        sA + (uint32_t)((a_row_base + mt * 16) * LDSW
                                        + ks * 16 + a_k_off) * 2);
            uint32_t b[2][4];
            #pragma unroll
            for (int jj = 0; jj < 2; jj++)
                ldsm_x4(b[jj][0], b[jj][1], b[jj][2], b[jj][3],
                        sB + (uint32_t)((b_row_base + jj * 16) * LDSW
                                        + ks * 16 + b_k_off) * 2);
            #pragma unroll
            for (int mt = 0; mt < 4; mt++)
                #pragma unroll
                for (int nf = 0; nf < 4; nf++)
                    mma16816(acc[mt][nf], a[mt], &b[nf >> 1][(nf & 1) * 2]);
        }
    }

    const int emb = m0 + wm * 64 + (lane >> 2);
    const int enb = n0 + wn * 32 + (lane & 3) * 2;
    #pragma unroll
    for (int mt = 0; mt < 4; mt++) {
        #pragma unroll
        for (int nf = 0; nf < 4; nf++) {
            const int en = enb + nf * 8;
            const int em0 = emb + mt * 16;
            float v0 = acc[mt][nf][0], v1 = acc[mt][nf][1];
            float v2 = acc[mt][nf][2], v3 = acc[mt][nf][3];
            if (MODE == 0) {
                float b0 = bias[en], b1 = bias[en + 1];
                *(float2*)(C + (size_t)em0 * N + en)       = make_float2(v0 + b0, v1 + b1);
                *(float2*)(C + (size_t)(em0 + 8) * N + en) = make_float2(v2 + b0, v3 + b1);
            } else {
                *(uint32_t*)(Ch + (size_t)em0 * N + en)       = pack_h2(v0, v1);
                *(uint32_t*)(Ch + (size_t)(em0 + 8) * N + en) = pack_h2(v2, v3);
            }
        }
    }
}

// ---------------------------------------------------------------------------
// Tensorized causal flash attention (fp16 mma, fp32 acc) — R16 verbatim.
// S = Q K^T (4 steps); O += P V (4 steps). 3-stage KV cp.async ring.
// Fully-masked warp-tiles skipped. Long blocks scheduled first.
// ---------------------------------------------------------------------------
#define LDK 72
#define QS_HALVES (128 * LDK)              // 9216
#define KVSTG_HALVES (2 * 64 * LDK)        // 9216
#define AT_BYTES ((QS_HALVES + 3 * KVSTG_HALVES) * 2)   // 73728

__global__ __launch_bounds__(256, 2)
void flash_attn_mma(const __half* __restrict__ qh, __half* __restrict__ ah)
{
    extern __shared__ __align__(128) __half hsm[];
    const uint32_t sQ = smem_u32(hsm);

    const int tid  = threadIdx.x;
    const int lane = tid & 31;
    const int warp = tid >> 5;
    const int bh = blockIdx.y;
    const int b  = bh >> 4;
    const int h  = bh & 15;
    const int m0 = ((int)gridDim.x - 1 - (int)blockIdx.x) * 128;  // long first

    const __half* Qh = qh + (size_t)b * SEQ * QKV_C + h * HDIM;
    const __half* Kh = Qh + CH;
    const __half* Vh = Qh + 2 * CH;

    auto kv_stage = [&](int s) -> uint32_t {
        return sQ + (uint32_t)(QS_HALVES + s * KVSTG_HALVES) * 2;
    };
    auto load_kv = [&](int t, int s) {
        const uint32_t sK = kv_stage(s);
        const uint32_t sV = sK + (uint32_t)(64 * LDK) * 2;
        #pragma unroll
        for (int i = 0; i < 2; i++) {
            int c = tid + i * 256;
            int r = c >> 3, j = (c & 7) * 8;
            size_t g = (size_t)(t * 64 + r) * QKV_C + j;
            CP_ASYNC16(sK + (uint32_t)(r * LDK + j) * 2, Kh + g);
            CP_ASYNC16(sV + (uint32_t)(r * LDK + j) * 2, Vh + g);
        }
    };

    #pragma unroll
    for (int i = 0; i < 4; i++) {
        int c = tid + i * 256;                // 0..1023
        int r = c >> 3, j = (c & 7) * 8;
        CP_ASYNC16(sQ + (uint32_t)(r * LDK + j) * 2,
                   Qh + (size_t)(m0 + r) * QKV_C + j);
    }
    load_kv(0, 0); CP_COMMIT();
    load_kv(1, 1); CP_COMMIT();

    const int lmat = lane >> 3;
    const int lrow = lane & 7;
    const int a_row = warp * 16 + ((lmat & 1) << 3) + lrow;
    const int a_k   = (lmat >> 1) << 3;
    const int bs_rb = ((lmat >> 1) << 3) + lrow;
    const int bs_k  = (lmat & 1) << 3;
    const int bv_r  = ((lmat & 1) << 3) + lrow;
    const int bv_c  = (lmat >> 1) << 3;

    float m_i[2] = {-1e30f, -1e30f};
    float l_i[2] = {0.0f, 0.0f};
    float oacc[8][4];
    #pragma unroll
    for (int nf = 0; nf < 8; nf++)
        #pragma unroll
        for (int q = 0; q < 4; q++) oacc[nf][q] = 0.0f;

    const int r0 = m0 + warp * 16 + (lane >> 2);
    const int r1 = r0 + 8;
    const int wmin = m0 + warp * 16;
    const int wmax = wmin + 15;

    const int ntiles = (m0 >> 6) + 2;
    for (int t = 0; t < ntiles; t++) {
        const int k0 = t << 6;
        CP_WAIT1();
        __syncthreads();
        if (t + 2 < ntiles) load_kv(t + 2, (t + 2) % 3);
        CP_COMMIT();

        if (k0 > wmax) continue;   // tile fully masked for this warp

        const uint32_t sK = kv_stage(t % 3);
        const uint32_t sV = sK + (uint32_t)(64 * LDK) * 2;

        // ---- S = Q K^T : 4 k16 steps ----
        float sacc[8][4];
        #pragma unroll
        for (int nf = 0; nf < 8; nf++)
            #pragma unroll
            for (int q = 0; q < 4; q++) sacc[nf][q] = 0.0f;

        #pragma unroll
        for (int s = 0; s < 4; s++) {
            const int kb = s * 16;
            uint32_t a[4];
            ldsm_x4(a[0], a[1], a[2], a[3],
                    sQ + (uint32_t)(a_row * LDK + kb + a_k) * 2);
            #pragma unroll
            for (int nt = 0; nt < 4; nt++) {
                uint32_t bb[4];
                ldsm_x4(bb[0], bb[1], bb[2], bb[3],
                        sK + (uint32_t)((nt * 16 + bs_rb) * LDK + kb + bs_k) * 2);
                mma16816(sacc[nt * 2],     a, &bb[0]);
                mma16816(sacc[nt * 2 + 1], a, &bb[2]);
            }
        }

        // ---- online softmax (mask vs warp's FIRST row) ----
        const bool need_mask = (k0 + 63 > wmin);
        float mx0 = -1e30f, mx1 = -1e30f;
        #pragma unroll
        for (int nf = 0; nf < 8; nf++) {
            const int cb = k0 + nf * 8 + ((lane & 3) << 1);
            float v0 = sacc[nf][0] * 0.125f;
            float v1 = sacc[nf][1] * 0.125f;
            float v2 = sacc[nf][2] * 0.125f;
            float v3 = sacc[nf][3] * 0.125f;
            if (need_mask) {
                if (cb     > r0) v0 = -1e30f;
                if (cb + 1 > r0) v1 = -1e30f;
                if (cb     > r1) v2 = -1e30f;
                if (cb + 1 > r1) v3 = -1e30f;
            }
            sacc[nf][0] = v0; sacc[nf][1] = v1;
            sacc[nf][2] = v2; sacc[nf][3] = v3;
            mx0 = fmaxf(mx0, fmaxf(v0, v1));
            mx1 = fmaxf(mx1, fmaxf(v2, v3));
        }
        mx0 = fmaxf(mx0, __shfl_xor_sync(0xffffffffu, mx0, 1));
        mx0 = fmaxf(mx0, __shfl_xor_sync(0xffffffffu, mx0, 2));
        mx1 = fmaxf(mx1, __shfl_xor_sync(0xffffffffu, mx1, 1));
        mx1 = fmaxf(mx1, __shfl_xor_sync(0xffffffffu, mx1, 2));

        const float mn0 = fmaxf(m_i[0], mx0);
        const float mn1 = fmaxf(m_i[1], mx1);
        const float cr0 = __expf(m_i[0] - mn0);
        const float cr1 = __expf(m_i[1] - mn1);
        m_i[0] = mn0; m_i[1] = mn1;

        float sm0 = 0.f, sm1 = 0.f;
        #pragma unroll
        for (int nf = 0; nf < 8; nf++) {
            float p0 = __expf(sacc[nf][0] - mn0);
            float p1 = __expf(sacc[nf][1] - mn0);
            float p2 = __expf(sacc[nf][2] - mn1);
            float p3 = __expf(sacc[nf][3] - mn1);
            sacc[nf][0] = p0; sacc[nf][1] = p1;
            sacc[nf][2] = p2; sacc[nf][3] = p3;
            sm0 += p0 + p1;  sm1 += p2 + p3;
        }
        sm0 += __shfl_xor_sync(0xffffffffu, sm0, 1);
        sm0 += __shfl_xor_sync(0xffffffffu, sm0, 2);
        sm1 += __shfl_xor_sync(0xffffffffu, sm1, 1);
        sm1 += __shfl_xor_sync(0xffffffffu, sm1, 2);
        l_i[0] = l_i[0] * cr0 + sm0;
        l_i[1] = l_i[1] * cr1 + sm1;
        #pragma unroll
        for (int nf = 0; nf < 8; nf++) {
            oacc[nf][0] *= cr0; oacc[nf][1] *= cr0;
            oacc[nf][2] *= cr1; oacc[nf][3] *= cr1;
        }

        // ---- O += P V : 4 k16 steps ----
        #pragma unroll
        for (int s = 0; s < 4; s++) {
            const int kb = s * 16;
            uint32_t pa[4];
            pa[0] = pack_h2(sacc[2 * s][0],     sacc[2 * s][1]);
            pa[1] = pack_h2(sacc[2 * s][2],     sacc[2 * s][3]);
            pa[2] = pack_h2(sacc[2 * s + 1][0], sacc[2 * s + 1][1]);
            pa[3] = pack_h2(sacc[2 * s + 1][2], sacc[2 * s + 1][3]);
            #pragma unroll
            for (int nt = 0; nt < 4; nt++) {
                uint32_t bb[4];
                ldsm_x4t(bb[0], bb[1], bb[2], bb[3],
                         sV + (uint32_t)((kb + bv_r) * LDK + nt * 16 + bv_c) * 2);
                mma16816(oacc[nt * 2],     pa, &bb[0]);
                mma16816(oacc[nt * 2 + 1], pa, &bb[2]);
            }
        }
    }

    // ---- epilogue: normalize + fp16 write to g_ah ----
    const float inv0 = 1.0f / l_i[0];
    const float inv1 = 1.0f / l_i[1];
    const size_t row0 = (size_t)(b * SEQ + r0) * CH;
    const size_t row1 = (size_t)(b * SEQ + r1) * CH;
    #pragma unroll
    for (int nf = 0; nf < 8; nf++) {
        const int col = h * HDIM + nf * 8 + ((lane & 3) << 1);
        *(uint32_t*)(ah + row0 + col) = pack_h2(oacc[nf][0] * inv0,
                                                oacc[nf][1] * inv0);
        *(uint32_t*)(ah + row1 + col) = pack_h2(oacc[nf][2] * inv1,
                                                oacc[nf][3] * inv1);
    }
}

// ---------------------------------------------------------------------------
extern "C" void kernel_launch(void* const* d_in, const int* in_sizes, int n_in,
                              void* d_out, int out_size)
{
    const float* x     = (const float*)d_in[0];
    const float* Wqkv  = (const float*)d_in[2];
    const float* Wproj = (const float*)d_in[3];
    const float* bproj = (const float*)d_in[4];
    float* out = (float*)d_out;

    void *p_qh, *p_xh, *p_ah, *p_wq, *p_wp;
    cudaGetSymbolAddress(&p_qh, g_qh);
    cudaGetSymbolAddress(&p_xh, g_xh);
    cudaGetSymbolAddress(&p_ah, g_ah);
    cudaGetSymbolAddress(&p_wq, g_wqkt);
    cudaGetSymbolAddress(&p_wp, g_wpt);
    __half* qh   = (__half*)p_qh;
    __half* xh   = (__half*)p_xh;
    __half* ah   = (__half*)p_ah;
    __half* wqkt = (__half*)p_wq;
    __half* wpt  = (__half*)p_wp;

    cudaFuncSetAttribute(gemm_mma<0>, cudaFuncAttributeMaxDynamicSharedMemorySize,
                         GSM_BYTES);
    cudaFuncSetAttribute(gemm_mma<1>, cudaFuncAttributeMaxDynamicSharedMemorySize,
                         GSM_BYTES);
    cudaFuncSetAttribute(flash_attn_mma, cudaFuncAttributeMaxDynamicSharedMemorySize,
                         AT_BYTES);

    // conversions
    round_flat<<<(ROWS * CH / 4 + 255) / 256, 256>>>(x, xh, ROWS * CH / 4);
    dim3 wt1(QKV_C / 32, CH / 32);
    roundT<<<wt1, dim3(32, 8)>>>(Wqkv, wqkt, QKV_C);
    dim3 wt2(CH / 32, CH / 32);
    roundT<<<wt2, dim3(32, 8)>>>(Wproj, wpt, CH);

    // 1) qkv = x @ Wqkv   (K=1024, 16 chunks of 64)
    dim3 g1(QKV_C / 128, ROWS / 128);
    gemm_mma<1><<<g1, 256, GSM_BYTES>>>(xh, CH, wqkt, CH, nullptr, nullptr,
                                        qh, QKV_C, CH / BK);

    // 2) causal flash attention -> fp16 proj input
    dim3 g2(SEQ / 128, BATCH * HEADS);
    flash_attn_mma<<<g2, 256, AT_BYTES>>>(qh, ah);

    // 3) out = attn @ Wproj + b   (K=1024, 16 chunks of 64)
    dim3 g3(CH / 128, ROWS / 128);
    gemm_mma<0><<<g3, 256, GSM_BYTES>>>(ah, CH, wpt, CH, bproj, out,
                                        nullptr, CH, CH / BK);
}